// round 17
// baseline (speedup 1.0000x reference)
#include <cuda_runtime.h>
#include <cuda_fp16.h>
#include <cstdint>

// ---------------------------------------------------------------------------
// Problem constants
// ---------------------------------------------------------------------------
#define IN_F   4096
#define OUT_F  4096
#define BLOCK_ 16
#define D_LAT  16
#define HID    64
#define KSIZE  65536
#define NB     (IN_F * OUT_F / BLOCK_)
#define M_ROWS 8192
#define K_DIM  4096
#define N_DIM  4096

// GEMM tiling: CTA 128x128, 4 warps of 64x64, BK=64, 3 stages (R5 config)
#define BM 128
#define BN 128
#define BK 64
#define STAGES 3
#define NK (K_DIM / BK)   // 64
#define THREADS 128

// ---------------------------------------------------------------------------
// Scratch
// ---------------------------------------------------------------------------
__device__ float  g_table[(size_t)KSIZE * BLOCK_];
__device__ __half g_Wh[(size_t)OUT_F * IN_F];
__device__ __half g_xh[(size_t)M_ROWS * IN_F];

// ---------------------------------------------------------------------------
// Helpers
// ---------------------------------------------------------------------------
__device__ __forceinline__ uint32_t smem_u32(const void* p) {
    return (uint32_t)__cvta_generic_to_shared(p);
}
#define SWZ(o) ((o) ^ (((o) >> 3) & 0x70))

__device__ __forceinline__ void cp16(uint32_t saddr, const void* gaddr) {
    asm volatile("cp.async.cg.shared.global [%0], [%1], 16;" :: "r"(saddr), "l"(gaddr));
}
#define CP_COMMIT() asm volatile("cp.async.commit_group;" ::: "memory")
#define CP_WAIT1()  asm volatile("cp.async.wait_group 1;" ::: "memory")

__device__ __forceinline__ void ldm_x4(uint32_t addr, uint32_t& r0, uint32_t& r1,
                                       uint32_t& r2, uint32_t& r3) {
    asm volatile("ldmatrix.sync.aligned.m8n8.x4.shared.b16 {%0,%1,%2,%3}, [%4];"
                 : "=r"(r0), "=r"(r1), "=r"(r2), "=r"(r3) : "r"(addr));
}

__device__ __forceinline__ void mma16816(float& c0, float& c1, float& c2, float& c3,
                                         uint32_t a0, uint32_t a1, uint32_t a2, uint32_t a3,
                                         uint32_t b0, uint32_t b1) {
    asm volatile("mma.sync.aligned.m16n8k16.row.col.f32.f16.f16.f32 "
                 "{%0,%1,%2,%3}, {%4,%5,%6,%7}, {%8,%9}, {%0,%1,%2,%3};"
                 : "+f"(c0), "+f"(c1), "+f"(c2), "+f"(c3)
                 : "r"(a0), "r"(a1), "r"(a2), "r"(a3), "r"(b0), "r"(b1));
}

// PDL primitives. Trigger: allow dependent grid to LAUNCH now.
// Sync: wait until preceding grid COMPLETES (memory visible).
__device__ __forceinline__ void grid_dep_sync() {
#if __CUDA_ARCH__ >= 900
    cudaGridDependencySynchronize();
#endif
}
__device__ __forceinline__ void grid_trigger_launch() {
#if __CUDA_ARCH__ >= 900
    cudaTriggerProgrammaticLaunchCompletion();
#endif
}

// ---------------------------------------------------------------------------
// Kernel 1: decode every codebook entry once (65536 x 16). R7-best config.
// Triggers PDL immediately so prep's xconv blocks overlap with this kernel.
// ---------------------------------------------------------------------------
__global__ void __launch_bounds__(256)
precompute_table(const float* __restrict__ codebook,
                 const float* __restrict__ W1, const float* __restrict__ b1,
                 const float* __restrict__ W2, const float* __restrict__ b2)
{
    grid_trigger_launch();   // dependent prep grid may launch now; its gather
                             // blocks still wait for THIS grid to complete.

    __shared__ float sW1[D_LAT * HID];
    __shared__ float sW2[HID * BLOCK_];
    __shared__ float sb1[HID];
    __shared__ float sb2[BLOCK_];

    const int tid = threadIdx.x;
    for (int i = tid; i < D_LAT * HID; i += 256) sW1[i] = W1[i];
    for (int i = tid; i < HID * BLOCK_; i += 256) sW2[i] = W2[i];
    if (tid < HID)    sb1[tid] = b1[tid];
    if (tid < BLOCK_) sb2[tid] = b2[tid];
    __syncthreads();

    const int e = blockIdx.x * 256 + tid;

    float c[D_LAT];
    const float4* cb = reinterpret_cast<const float4*>(codebook + (size_t)e * D_LAT);
    {
        float4 v0 = cb[0], v1 = cb[1], v2 = cb[2], v3 = cb[3];
        c[0]=v0.x; c[1]=v0.y; c[2]=v0.z; c[3]=v0.w;
        c[4]=v1.x; c[5]=v1.y; c[6]=v1.z; c[7]=v1.w;
        c[8]=v2.x; c[9]=v2.y; c[10]=v2.z; c[11]=v2.w;
        c[12]=v3.x; c[13]=v3.y; c[14]=v3.z; c[15]=v3.w;
    }

    float h[HID];
    #pragma unroll
    for (int j = 0; j < HID; ++j) h[j] = sb1[j];
    #pragma unroll
    for (int d = 0; d < D_LAT; ++d) {
        const float cd = c[d];
        #pragma unroll
        for (int j = 0; j < HID; ++j) h[j] = fmaf(cd, sW1[d * HID + j], h[j]);
    }
    #pragma unroll
    for (int j = 0; j < HID; ++j) h[j] = fmaxf(h[j], 0.0f);

    float blk[BLOCK_];
    #pragma unroll
    for (int k = 0; k < BLOCK_; ++k) blk[k] = sb2[k];
    #pragma unroll
    for (int j = 0; j < HID; ++j) {
        const float hj = h[j];
        #pragma unroll
        for (int k = 0; k < BLOCK_; ++k) blk[k] = fmaf(hj, sW2[j * BLOCK_ + k], blk[k]);
    }

    float4* dst = reinterpret_cast<float4*>(g_table + (size_t)e * BLOCK_);
    dst[0] = make_float4(blk[0], blk[1], blk[2], blk[3]);
    dst[1] = make_float4(blk[4], blk[5], blk[6], blk[7]);
    dst[2] = make_float4(blk[8], blk[9], blk[10], blk[11]);
    dst[3] = make_float4(blk[12], blk[13], blk[14], blk[15]);
}

// ---------------------------------------------------------------------------
// Kernel 2 (fused, PDL-overlapped with kernel 1):
//   blocks [0, XCONV_BLOCKS): x -> fp16  (independent of table, no wait)
//   blocks [XCONV_BLOCKS, +OUT_F): W gather (grid_dep_sync before g_table)
// Triggers its own PDL early so the GEMM's launch gap is hidden.
// ---------------------------------------------------------------------------
#define XCONV_BLOCKS ((M_ROWS * K_DIM) / (256 * 16))   // 8192

__global__ void __launch_bounds__(256)
prep_kernel(const int* __restrict__ idx,
            const float* __restrict__ scale, const float* __restrict__ shift,
            const float* __restrict__ x)
{
    grid_trigger_launch();   // GEMM grid may launch; it grid_dep_syncs anyway.

    if (blockIdx.x < XCONV_BLOCKS) {
        const size_t t = (size_t)blockIdx.x * 256 + threadIdx.x;
        const size_t base = t * 16;
        float4 a0 = *reinterpret_cast<const float4*>(x + base);
        float4 a1 = *reinterpret_cast<const float4*>(x + base + 4);
        float4 a2 = *reinterpret_cast<const float4*>(x + base + 8);
        float4 a3 = *reinterpret_cast<const float4*>(x + base + 12);
        __align__(16) __half h[16];
        h[0] =__float2half_rn(a0.x); h[1] =__float2half_rn(a0.y);
        h[2] =__float2half_rn(a0.z); h[3] =__float2half_rn(a0.w);
        h[4] =__float2half_rn(a1.x); h[5] =__float2half_rn(a1.y);
        h[6] =__float2half_rn(a1.z); h[7] =__float2half_rn(a1.w);
        h[8] =__float2half_rn(a2.x); h[9] =__float2half_rn(a2.y);
        h[10]=__float2half_rn(a2.z); h[11]=__float2half_rn(a2.w);
        h[12]=__float2half_rn(a3.x); h[13]=__float2half_rn(a3.y);
        h[14]=__float2half_rn(a3.z); h[15]=__float2half_rn(a3.w);
        reinterpret_cast<uint4*>(g_xh + base)[0] = reinterpret_cast<uint4*>(h)[0];
        reinterpret_cast<uint4*>(g_xh + base)[1] = reinterpret_cast<uint4*>(h)[1];
    } else {
        grid_dep_sync();     // wait for precompute_table to COMPLETE

        const int o = blockIdx.x - XCONV_BLOCKS;
        const float s  = __ldg(scale + o);
        const float sh = __ldg(shift + o);

        const int b = o * 256 + threadIdx.x;
        const int e = idx[b];

        const float4* src = reinterpret_cast<const float4*>(g_table + (size_t)e * BLOCK_);
        float4 v0 = src[0], v1 = src[1], v2 = src[2], v3 = src[3];
        float blk[16] = {v0.x,v0.y,v0.z,v0.w, v1.x,v1.y,v1.z,v1.w,
                         v2.x,v2.y,v2.z,v2.w, v3.x,v3.y,v3.z,v3.w};

        __align__(16) __half h16[16];
        #pragma unroll
        for (int q = 0; q < 16; ++q) h16[q] = __float2half_rn(fmaf(blk[q], s, sh));

        const size_t base = (size_t)o * IN_F + (size_t)threadIdx.x * 16;
        reinterpret_cast<uint4*>(g_Wh + base)[0] = reinterpret_cast<uint4*>(h16)[0];
        reinterpret_cast<uint4*>(g_Wh + base)[1] = reinterpret_cast<uint4*>(h16)[1];
    }
}

// ---------------------------------------------------------------------------
// Kernel 3: fp16 mma.sync GEMM — R13 body; PDL sync deferred past setup so
// CTA-local initialization overlaps prep's tail.
// ---------------------------------------------------------------------------
#define STG_BYTES 32768
#define SMEM_TOTAL (STAGES * STG_BYTES)   // 96 KB; 2 CTAs/SM

__device__ __forceinline__ void load_stage(uint32_t sbase, int buf, int it,
                                           int bm0, int bn0, int tid)
{
    const uint32_t sA = sbase + buf * STG_BYTES;
    const uint32_t sB = sA + 16384;
    const size_t k0 = (size_t)it * BK;
    #pragma unroll
    for (int i = 0; i < 8; ++i) {
        const int c = tid + i * 128;          // 0..1023
        const int row = c >> 3;
        const int cx  = c & 7;
        const uint32_t soff = SWZ((uint32_t)(row * 128 + cx * 16));
        cp16(sA + soff, g_xh + (size_t)(bm0 + row) * K_DIM + k0 + cx * 8);
        cp16(sB + soff, g_Wh + (size_t)(bn0 + row) * K_DIM + k0 + cx * 8);
    }
}

__global__ void __launch_bounds__(THREADS, 2)
gemm_kernel(const float* __restrict__ bias, float* __restrict__ C)
{
    extern __shared__ char smem[];
    const uint32_t sbase = smem_u32(smem);
    const int tid  = threadIdx.x;
    const int lane = tid & 31;
    const int w    = tid >> 5;          // 0..3
    const int wm   = w >> 1;            // m offset wm*64
    const int wn   = w & 1;             // n offset wn*64
    const int bm0  = blockIdx.y * BM;
    const int bn0  = blockIdx.x * BN;

    float acc[4][8][4];
    #pragma unroll
    for (int mt = 0; mt < 4; ++mt)
        #pragma unroll
        for (int nt = 0; nt < 8; ++nt)
            #pragma unroll
            for (int q = 0; q < 4; ++q) acc[mt][nt][q] = 0.0f;

    // Per-lane ldmatrix base offsets (computed before the dependency wait)
    const int a_row = wm * 64 + (lane & 15);
    const int a_cb  = ((lane >> 4) & 1) * 16;
    const int b_row = wn * 64 + ((lane >> 4) & 1) * 8 + (lane & 7);
    const int b_cb  = ((lane >> 3) & 1) * 16;

    grid_dep_sync();   // PDL: wait for prep completion before reading g_xh/g_Wh

    // Prologue: fill 2 of 3 buffers
    load_stage(sbase, 0, 0, bm0, bn0, tid);
    CP_COMMIT();
    load_stage(sbase, 1, 1, bm0, bn0, tid);
    CP_COMMIT();

    for (int it = 0; it < NK; ++it) {
        CP_WAIT1();
        __syncthreads();   // sole barrier: proves iter it-1 reads complete

        const int buf = it % STAGES;
        const uint32_t sA = sbase + buf * STG_BYTES;
        const uint32_t sB = sA + 16384;

        uint32_t a[2][4][4];
        uint32_t b[2][8][2];

        // Load kk=0 fragments
        #pragma unroll
        for (int mt = 0; mt < 4; ++mt) {
            const uint32_t off = (uint32_t)((a_row + mt * 16) * 128 + a_cb);
            ldm_x4(sA + SWZ(off), a[0][mt][0], a[0][mt][1], a[0][mt][2], a[0][mt][3]);
        }
        #pragma unroll
        for (int ntp = 0; ntp < 4; ++ntp) {
            const uint32_t off = (uint32_t)((b_row + ntp * 16) * 128 + b_cb);
            uint32_t r0, r1, r2, r3;
            ldm_x4(sB + SWZ(off), r0, r1, r2, r3);
            b[0][ntp*2+0][0] = r0; b[0][ntp*2+0][1] = r1;
            b[0][ntp*2+1][0] = r2; b[0][ntp*2+1][1] = r3;
        }

        // Issue next stage's cp.async (after the barrier -> buffer reuse safe)
        const int nxt = it + 2;
        if (nxt < NK) load_stage(sbase, nxt % STAGES, nxt, bm0, bn0, tid);
        CP_COMMIT();

        #pragma unroll
        for (int kk = 0; kk < 4; ++kk) {
            const int cur = kk & 1;
            const int nxb = cur ^ 1;
            if (kk < 3) {
                const int kc = (kk + 1) * 32;
                #pragma unroll
                for (int mt = 0; mt < 4; ++mt) {
                    const uint32_t off = (uint32_t)((a_row + mt * 16) * 128 + kc + a_cb);
                    ldm_x4(sA + SWZ(off), a[nxb][mt][0], a[nxb][mt][1], a[nxb][mt][2], a[nxb][mt][3]);
                }
                #pragma unroll
                for (int ntp = 0; ntp < 4; ++ntp) {
                    const uint32_t off = (uint32_t)((b_row + ntp * 16) * 128 + kc + b_cb);
                    uint32_t r0, r1, r2, r3;
                    ldm_x4(sB + SWZ(off), r0, r1, r2, r3);
                    b[nxb][ntp*2+0][0] = r0; b[nxb][ntp*2+0][1] = r1;
                    b[nxb][ntp*2+1][0] = r2; b[nxb][ntp*2+1][1] = r3;
                }
            }
            #pragma unroll
            for (int mt = 0; mt < 4; ++mt)
                #pragma unroll
                for (int nt = 0; nt < 8; ++nt)
                    mma16816(acc[mt][nt][0], acc[mt][nt][1], acc[mt][nt][2], acc[mt][nt][3],
                             a[cur][mt][0], a[cur][mt][1], a[cur][mt][2], a[cur][mt][3],
                             b[cur][nt][0], b[cur][nt][1]);
        }
    }

    // Epilogue
    #pragma unroll
    for (int nt = 0; nt < 8; ++nt) {
        const int col = bn0 + wn * 64 + nt * 8 + (lane & 3) * 2;
        const float bx = __ldg(bias + col);
        const float by = __ldg(bias + col + 1);
        #pragma unroll
        for (int mt = 0; mt < 4; ++mt) {
            const int r0 = bm0 + wm * 64 + mt * 16 + (lane >> 2);
            float2 v0 = make_float2(acc[mt][nt][0] + bx, acc[mt][nt][1] + by);
            float2 v1 = make_float2(acc[mt][nt][2] + bx, acc[mt][nt][3] + by);
            *reinterpret_cast<float2*>(C + (size_t)r0 * N_DIM + col) = v0;
            *reinterpret_cast<float2*>(C + (size_t)(r0 + 8) * N_DIM + col) = v1;
        }
    }
}

// ---------------------------------------------------------------------------
// kernel_launch — PDL chain with early triggers (R16 structure).
// ---------------------------------------------------------------------------
extern "C" void kernel_launch(void* const* d_in, const int* in_sizes, int n_in,
                              void* d_out, int out_size)
{
    const float* x        = (const float*)d_in[0];
    const int*   y_in_idx = (const int*)  d_in[1];
    const float* codebook = (const float*)d_in[2];
    const float* W1       = (const float*)d_in[3];
    const float* b1       = (const float*)d_in[4];
    const float* W2       = (const float*)d_in[5];
    const float* b2       = (const float*)d_in[6];
    const float* scale    = (const float*)d_in[7];
    const float* shift    = (const float*)d_in[8];
    const float* bias     = (const float*)d_in[9];
    float* out = (float*)d_out;

    cudaFuncSetAttribute(gemm_kernel, cudaFuncAttributeMaxDynamicSharedMemorySize, SMEM_TOTAL);

    // 1) decode each codebook entry once (triggers PDL at entry)
    precompute_table<<<KSIZE / 256, 256>>>(codebook, W1, b1, W2, b2);

    // 2) prep (PDL: launches while table still runs; gather blocks wait)
    {
        cudaLaunchAttribute attrs[1];
        attrs[0].id = cudaLaunchAttributeProgrammaticStreamSerialization;
        attrs[0].val.programmaticStreamSerializationAllowed = 1;
        cudaLaunchConfig_t cfg = {};
        cfg.gridDim  = dim3(XCONV_BLOCKS + OUT_F, 1, 1);
        cfg.blockDim = dim3(256, 1, 1);
        cfg.attrs = attrs;
        cfg.numAttrs = 1;
        cudaLaunchKernelEx(&cfg, prep_kernel, y_in_idx, scale, shift, x);
    }

    // 3) GEMM (PDL: early launch; setup overlaps prep tail, then syncs)
    {
        cudaLaunchAttribute attrs[1];
        attrs[0].id = cudaLaunchAttributeProgrammaticStreamSerialization;
        attrs[0].val.programmaticStreamSerializationAllowed = 1;
        cudaLaunchConfig_t cfg = {};
        cfg.gridDim  = dim3(N_DIM / BN, M_ROWS / BM, 1);
        cfg.blockDim = dim3(THREADS, 1, 1);
        cfg.dynamicSmemBytes = SMEM_TOTAL;
        cfg.attrs = attrs;
        cfg.numAttrs = 1;
        cudaLaunchKernelEx(&cfg, gemm_kernel, bias, out);
    }
}